// round 8
// baseline (speedup 1.0000x reference)
#include <cuda_runtime.h>

#define B_ 32
#define H_ 3
#define M_ 2048
#define D_ 512
#define L_ 32
#define T_ 2049

#define NCHUNK 32
#define CHUNK (M_ / NCHUNK)   // 64 memories per chunk

// Scratch
__device__ float g_opart[B_ * NCHUNK * D_];    // per-chunk weighted val partials (unnormalized)
__device__ float g_cmax[B_ * NCHUNK];          // per-chunk logit max
__device__ float g_csum[B_ * NCHUNK];          // per-chunk exp-sum (rel. to chunk max)

// ---------------------------------------------------------------------------
// u0[b,d] = sum_l B_emb[query[b,l], d] * pos_enc[l, d]
// ---------------------------------------------------------------------------
__global__ void u0_kernel(const int* __restrict__ query,
                          const float* __restrict__ Bemb,
                          const float* __restrict__ pos,
                          float* __restrict__ u) {
    __shared__ int sq[L_];
    int b = blockIdx.x, d = threadIdx.x;
    if (d < L_) sq[d] = query[b * L_ + d];
    __syncthreads();
    float acc = 0.f;
#pragma unroll
    for (int l = 0; l < L_; ++l)
        acc += Bemb[(size_t)sq[l] * D_ + d] * pos[l * D_ + d];
    u[b * D_ + d] = acc;
}

// ---------------------------------------------------------------------------
// Fused hop kernel: block (c,b) owns memories [c*64, c*64+64).
//  Phase 1 (logits): warp w computes logit for its 8 m's:
//      l_m = dot(key[b,hop,m,:] + TA[hop, rt[b,m], :], u[b,:])
//  Phase 2 (online softmax, chunk-local): cmax, ex_m = exp(l_m - cmax), csum.
//  Phase 3 (weighted val): o[b,c,d] = sum_m ex_m * (val[b,hop,m,d] + TC[hop,rt,d])
// grid: (NCHUNK, B), block 256.
// ---------------------------------------------------------------------------
__global__ void __launch_bounds__(256) hop_kernel(int hop,
                            const float* __restrict__ key,
                            const float* __restrict__ val,
                            const float* __restrict__ TA,
                            const float* __restrict__ TC,
                            const int* __restrict__ rt,
                            const float* __restrict__ u) {
    int b = blockIdx.y, c = blockIdx.x;
    int tid = threadIdx.x;
    int warp = tid >> 5, lane = tid & 31;

    __shared__ float4 su[D_ / 4];     // u row
    __shared__ float  sl[CHUNK];      // chunk logits
    __shared__ float  ex[CHUNK];      // chunk exp weights
    __shared__ int    st[CHUNK];      // chunk rel_time
    __shared__ float4 sacc[D_ / 4];

    if (tid < D_ / 4) su[tid] = ((const float4*)(u + b * D_))[tid];
    if (tid < CHUNK)  st[tid] = rt[b * M_ + c * CHUNK + tid];
    __syncthreads();

    // ---- Phase 1: logits (warp per m, 8 m's per warp) -------------------
    const float4* kchunk = (const float4*)(key + ((size_t)(b * H_ + hop) * M_ + c * CHUNK) * D_);
    const float4* tabase = (const float4*)(TA + (size_t)hop * T_ * D_);
#pragma unroll
    for (int j = 0; j < CHUNK / 8; ++j) {
        int ml = warp + 8 * j;                       // local m in [0,64)
        const float4* krow = kchunk + (size_t)ml * (D_ / 4);
        const float4* trow = tabase + (size_t)st[ml] * (D_ / 4);
        float acc = 0.f;
#pragma unroll
        for (int k = 0; k < 4; ++k) {
            int idx = lane + 32 * k;
            float4 kv = __ldcs(krow + idx);
            float4 tv = __ldg(trow + idx);
            float4 uv = su[idx];
            acc += (kv.x + tv.x) * uv.x + (kv.y + tv.y) * uv.y
                 + (kv.z + tv.z) * uv.z + (kv.w + tv.w) * uv.w;
        }
#pragma unroll
        for (int o = 16; o; o >>= 1) acc += __shfl_down_sync(0xffffffffu, acc, o);
        if (lane == 0) sl[ml] = acc;
    }
    __syncthreads();

    // ---- Phase 2: chunk-local online softmax ----------------------------
    if (tid < CHUNK) {
        float cm = sl[0];
#pragma unroll
        for (int i = 1; i < CHUNK; ++i) cm = fmaxf(cm, sl[i]);
        ex[tid] = __expf(sl[tid] - cm);
        if (tid == 0) g_cmax[b * NCHUNK + c] = cm;
    }
    __syncthreads();
    if (tid == 255) {
        float s = 0.f;
#pragma unroll
        for (int i = 0; i < CHUNK; ++i) s += ex[i];
        g_csum[b * NCHUNK + c] = s;
    }

    // ---- Phase 3: weighted val partial ----------------------------------
    int d4 = tid & 127, grp = tid >> 7;
    const float4* vbase  = (const float4*)(val + ((size_t)(b * H_ + hop) * M_ + c * CHUNK) * D_);
    const float4* tcbase = (const float4*)(TC + (size_t)hop * T_ * D_);

    float4 acc = make_float4(0.f, 0.f, 0.f, 0.f);
#pragma unroll 4
    for (int mm = grp; mm < CHUNK; mm += 2) {
        float pm = ex[mm];
        float4 vv = __ldcs(vbase + (size_t)mm * (D_ / 4) + d4);
        float4 tv = __ldg(tcbase + (size_t)st[mm] * (D_ / 4) + d4);
        acc.x += (vv.x + tv.x) * pm;
        acc.y += (vv.y + tv.y) * pm;
        acc.z += (vv.z + tv.z) * pm;
        acc.w += (vv.w + tv.w) * pm;
    }

    if (grp == 1) sacc[d4] = acc;
    __syncthreads();
    if (grp == 0) {
        float4 o = sacc[d4];
        acc.x += o.x; acc.y += o.y; acc.z += o.z; acc.w += o.w;
        ((float4*)(g_opart + ((size_t)b * NCHUNK + c) * D_))[d4] = acc;
    }
}

// ---------------------------------------------------------------------------
// Combine: gmax = max_c cmax; Z = sum_c csum_c*exp(cmax_c-gmax);
//          u[b,d] += ( sum_c o[b,c,d]*exp(cmax_c-gmax) ) / Z
// grid: (B,4), block 128 — per-b stats recomputed per block (32 values, free).
// ---------------------------------------------------------------------------
__global__ void combine_kernel(float* __restrict__ u) {
    int b = blockIdx.x, tid = threadIdx.x;
    __shared__ float ecf[NCHUNK];
    __shared__ float sinvZ;

    if (tid < NCHUNK) {
        float gm = g_cmax[b * NCHUNK];
#pragma unroll
        for (int i = 1; i < NCHUNK; ++i) gm = fmaxf(gm, g_cmax[b * NCHUNK + i]);
        float e = __expf(g_cmax[b * NCHUNK + tid] - gm);
        ecf[tid] = e;
        if (tid == 0) {
            float Z = 0.f;
#pragma unroll
            for (int i = 0; i < NCHUNK; ++i)
                Z += g_csum[b * NCHUNK + i] * __expf(g_cmax[b * NCHUNK + i] - gm);
            sinvZ = 1.f / Z;
        }
    }
    __syncthreads();
    float invZ = sinvZ;

    int d = blockIdx.y * 128 + tid;
    float acc = 0.f;
#pragma unroll
    for (int c = 0; c < NCHUNK; ++c)
        acc += g_opart[((size_t)b * NCHUNK + c) * D_ + d] * ecf[c];
    u[b * D_ + d] += acc * invZ;
}

// ---------------------------------------------------------------------------
extern "C" void kernel_launch(void* const* d_in, const int* in_sizes, int n_in,
                              void* d_out, int out_size) {
    const int*   query = (const int*)d_in[0];
    const int*   rt    = (const int*)d_in[1];
    const float* key   = (const float*)d_in[2];
    const float* val   = (const float*)d_in[3];
    const float* Bemb  = (const float*)d_in[4];
    const float* TA    = (const float*)d_in[5];
    const float* TC    = (const float*)d_in[6];
    const float* pos   = (const float*)d_in[7];
    float* u = (float*)d_out;   // [B, D]

    u0_kernel<<<B_, D_>>>(query, Bemb, pos, u);
    for (int hop = 0; hop < H_; ++hop) {
        hop_kernel<<<dim3(NCHUNK, B_), 256>>>(hop, key, val, TA, TC, rt, u);
        combine_kernel<<<dim3(B_, 4), 128>>>(u);
    }
}

// round 11
// speedup vs baseline: 1.2290x; 1.2290x over previous
#include <cuda_runtime.h>

#define B_ 32
#define H_ 3
#define M_ 2048
#define D_ 512
#define L_ 32
#define T_ 2049

#define NCHUNK 32
#define CHUNK (M_ / NCHUNK)   // 64 memories per chunk

// Scratch
__device__ float g_logits[B_ * M_];            // raw logits
__device__ float g_opart[B_ * NCHUNK * D_];    // per-chunk weighted val partials (unnormalized)
__device__ float g_cmax[B_ * NCHUNK];          // per-chunk logit max
__device__ float g_csum[B_ * NCHUNK];          // per-chunk exp-sum (rel. to chunk max)

// ---------------------------------------------------------------------------
// u0[b,d] = sum_l B_emb[query[b,l], d] * pos_enc[l, d]
// ---------------------------------------------------------------------------
__global__ void u0_kernel(const int* __restrict__ query,
                          const float* __restrict__ Bemb,
                          const float* __restrict__ pos,
                          float* __restrict__ u) {
    __shared__ int sq[L_];
    int b = blockIdx.x, d = threadIdx.x;
    if (d < L_) sq[d] = query[b * L_ + d];
    __syncthreads();
    float acc = 0.f;
#pragma unroll
    for (int l = 0; l < L_; ++l)
        acc += Bemb[(size_t)sq[l] * D_ + d] * pos[l * D_ + d];
    u[b * D_ + d] = acc;
}

// ---------------------------------------------------------------------------
// logit[b,m] = dot( key[b,hop,m,:] + TA[hop, rt[b,m], :], u[b,:] )
// grid: (M/8, B), block 256 (one warp per row m).  [R4/R7-proven]
// ---------------------------------------------------------------------------
__global__ void __launch_bounds__(256) logits_kernel(int hop,
                              const float* __restrict__ key,
                              const float* __restrict__ TA,
                              const int* __restrict__ rt,
                              const float* __restrict__ u) {
    __shared__ float4 su[D_ / 4];
    int b = blockIdx.y;
    int tid = threadIdx.x;
    if (tid < D_ / 4) su[tid] = ((const float4*)(u + b * D_))[tid];
    __syncthreads();

    int warp = tid >> 5, lane = tid & 31;
    int m = blockIdx.x * 8 + warp;
    int t = rt[b * M_ + m];

    const float4* krow = (const float4*)(key + ((size_t)(b * H_ + hop) * M_ + m) * D_);
    const float4* trow = (const float4*)(TA + ((size_t)hop * T_ + t) * D_);

    float acc = 0.f;
#pragma unroll
    for (int k = 0; k < 4; ++k) {
        int idx = lane + 32 * k;
        float4 kv = __ldcs(krow + idx);
        float4 tv = __ldg(trow + idx);
        float4 uv = su[idx];
        acc += (kv.x + tv.x) * uv.x + (kv.y + tv.y) * uv.y
             + (kv.z + tv.z) * uv.z + (kv.w + tv.w) * uv.w;
    }
#pragma unroll
    for (int o = 16; o; o >>= 1) acc += __shfl_down_sync(0xffffffffu, acc, o);
    if (lane == 0) g_logits[b * M_ + m] = acc;
}

// ---------------------------------------------------------------------------
// Online-softmax outpart: per chunk c,
//   cmax = max_{m in c} logit,  ex_m = exp(logit_m - cmax),  csum = sum ex_m
//   o[b,c,d] = sum_m ex_m * (val[b,hop,m,d] + TC[hop,rt,d])
// grid: (NCHUNK, B), block 256.  [R7-proven, exp-sum now warp-parallel]
// ---------------------------------------------------------------------------
__global__ void __launch_bounds__(256) outpartOS_kernel(int hop,
                               const float* __restrict__ val,
                               const float* __restrict__ TC,
                               const int* __restrict__ rt) {
    int b = blockIdx.y, c = blockIdx.x;
    int tid = threadIdx.x;
    int d4 = tid & 127, grp = tid >> 7;

    __shared__ float sl[CHUNK];
    __shared__ float ex[CHUNK];
    __shared__ int   st[CHUNK];
    __shared__ float4 sacc[D_ / 4];

    if (tid < CHUNK) {
        sl[tid] = g_logits[b * M_ + c * CHUNK + tid];
        st[tid] = rt[b * M_ + c * CHUNK + tid];
    }
    __syncthreads();

    // chunk-local max + exp (threads < CHUNK, redundant max via smem)
    if (tid < CHUNK) {
        float cm = sl[0];
#pragma unroll
        for (int i = 1; i < CHUNK; ++i) cm = fmaxf(cm, sl[i]);
        ex[tid] = __expf(sl[tid] - cm);
        if (tid == 0) g_cmax[b * NCHUNK + c] = cm;
    }
    __syncthreads();

    // chunk exp-sum: warp-parallel in the last warp (lanes sum 2, shfl-reduce)
    if (tid >= 224) {
        int lane = tid & 31;
        float s = ex[lane] + ex[lane + 32];
#pragma unroll
        for (int o = 16; o; o >>= 1) s += __shfl_down_sync(0xffffffffu, s, o);
        if (lane == 0) g_csum[b * NCHUNK + c] = s;
    }

    const float4* vbase  = (const float4*)(val + ((size_t)(b * H_ + hop) * M_ + c * CHUNK) * D_);
    const float4* tcbase = (const float4*)(TC + (size_t)hop * T_ * D_);

    float4 acc = make_float4(0.f, 0.f, 0.f, 0.f);
#pragma unroll 4
    for (int mm = grp; mm < CHUNK; mm += 2) {
        float pm = ex[mm];
        float4 vv = __ldcs(vbase + (size_t)mm * (D_ / 4) + d4);
        float4 tv = __ldg(tcbase + (size_t)st[mm] * (D_ / 4) + d4);
        acc.x += (vv.x + tv.x) * pm;
        acc.y += (vv.y + tv.y) * pm;
        acc.z += (vv.z + tv.z) * pm;
        acc.w += (vv.w + tv.w) * pm;
    }

    if (grp == 1) sacc[d4] = acc;
    __syncthreads();
    if (grp == 0) {
        float4 o = sacc[d4];
        acc.x += o.x; acc.y += o.y; acc.z += o.z; acc.w += o.w;
        ((float4*)(g_opart + ((size_t)b * NCHUNK + c) * D_))[d4] = acc;
    }
}

// ---------------------------------------------------------------------------
// Combine: gmax = max_c cmax; Z = sum_c csum_c*exp(cmax_c-gmax);
//          u[b,d] += ( sum_c o[b,c,d]*exp(cmax_c-gmax) ) / Z
// grid: (B,4), block 128 — per-b stats recomputed per block (32 values, free).
// [R8-proven widened combine]
// ---------------------------------------------------------------------------
__global__ void combine_kernel(float* __restrict__ u) {
    int b = blockIdx.x, tid = threadIdx.x;
    __shared__ float ecf[NCHUNK];
    __shared__ float sinvZ;

    if (tid < NCHUNK) {
        float gm = g_cmax[b * NCHUNK];
#pragma unroll
        for (int i = 1; i < NCHUNK; ++i) gm = fmaxf(gm, g_cmax[b * NCHUNK + i]);
        float e = __expf(g_cmax[b * NCHUNK + tid] - gm);
        ecf[tid] = e;
        if (tid == 0) {
            float Z = 0.f;
#pragma unroll
            for (int i = 0; i < NCHUNK; ++i)
                Z += g_csum[b * NCHUNK + i] * __expf(g_cmax[b * NCHUNK + i] - gm);
            sinvZ = 1.f / Z;
        }
    }
    __syncthreads();
    float invZ = sinvZ;

    int d = blockIdx.y * 128 + tid;
    float acc = 0.f;
#pragma unroll
    for (int c = 0; c < NCHUNK; ++c)
        acc += g_opart[((size_t)b * NCHUNK + c) * D_ + d] * ecf[c];
    u[b * D_ + d] += acc * invZ;
}

// ---------------------------------------------------------------------------
extern "C" void kernel_launch(void* const* d_in, const int* in_sizes, int n_in,
                              void* d_out, int out_size) {
    const int*   query = (const int*)d_in[0];
    const int*   rt    = (const int*)d_in[1];
    const float* key   = (const float*)d_in[2];
    const float* val   = (const float*)d_in[3];
    const float* Bemb  = (const float*)d_in[4];
    const float* TA    = (const float*)d_in[5];
    const float* TC    = (const float*)d_in[6];
    const float* pos   = (const float*)d_in[7];
    float* u = (float*)d_out;   // [B, D]

    u0_kernel<<<B_, D_>>>(query, Bemb, pos, u);
    for (int hop = 0; hop < H_; ++hop) {
        logits_kernel<<<dim3(M_ / 8, B_), 256>>>(hop, key, TA, rt, u);
        outpartOS_kernel<<<dim3(NCHUNK, B_), 256>>>(hop, val, TC, rt);
        combine_kernel<<<dim3(B_, 4), 128>>>(u);
    }
}